// round 4
// baseline (speedup 1.0000x reference)
#include <cuda_runtime.h>
#include <math_constants.h>

#define N_TOTAL 32768
#define DIM     256
#define KCODES  1024
#define HW      1024
#define TN      128   // n rows per block in argmin kernel
#define TKP     128   // k panel
#define TC      8     // c chunk

__device__ float  g_rowsq[N_TOTAL];
__device__ float  g_embsq[KCODES];
__device__ int    g_idx[N_TOTAL];
__device__ double g_partial[256];

// a_n = sum_c fl(x^2)  (square rounded, then summed — matches jnp.sum(flat**2))
__global__ void k_rowsq(const float* __restrict__ x) {
    int n = blockIdx.x * blockDim.x + threadIdx.x;
    if (n >= N_TOTAL) return;
    int b = n >> 10, hw = n & 1023;
    const float* p = x + (size_t)b * DIM * HW + hw;
    float acc = 0.f;
#pragma unroll 8
    for (int c = 0; c < DIM; c++) {
        float v = p[c * HW];
        acc = __fadd_rn(acc, __fmul_rn(v, v));
    }
    g_rowsq[n] = acc;
}

__global__ void k_embsq(const float* __restrict__ e) {
    int k = blockIdx.x * blockDim.x + threadIdx.x;
    if (k >= KCODES) return;
    const float* p = e + (size_t)k * DIM;
    float acc = 0.f;
#pragma unroll 8
    for (int c = 0; c < DIM; c++) {
        float v = p[c];
        acc = __fadd_rn(acc, __fmul_rn(v, v));
    }
    g_embsq[k] = acc;
}

__global__ void k_zero(float* __restrict__ out, long long count) {
    long long i = (long long)blockIdx.x * blockDim.x + threadIdx.x;
    if (i < count) out[i] = 0.0f;
}

// Fused fp32 GEMM (scores) + rounded-distance argmin. One block: 128 rows x all 1024 codes.
__global__ __launch_bounds__(256) void k_argmin(const float* __restrict__ x,
                                                const float* __restrict__ emb) {
    __shared__ __align__(16) float As[TC][132];
    __shared__ __align__(16) float Bs[TC][132];
    __shared__ float sBest[TN];
    __shared__ int   sBIdx[TN];
    __shared__ float sA[TN];

    int tid = threadIdx.x;
    int tx = tid & 15, ty = tid >> 4;
    int n0 = blockIdx.x * TN;
    int b = n0 >> 10, hw0 = n0 & 1023;
    const float* xb = x + (size_t)b * DIM * HW + hw0;

    if (tid < TN) {
        sBest[tid] = CUDART_INF_F;
        sBIdx[tid] = 0;
        sA[tid]    = g_rowsq[n0 + tid];
    }

    for (int k0 = 0; k0 < KCODES; k0 += TKP) {
        float acc[8][8];
#pragma unroll
        for (int i = 0; i < 8; i++)
#pragma unroll
            for (int j = 0; j < 8; j++) acc[i][j] = 0.f;

        for (int c0 = 0; c0 < DIM; c0 += TC) {
            __syncthreads();
            // A tile: [TC][128], coalesced over n
#pragma unroll
            for (int r = 0; r < 4; r++) {
                int idx = tid + r * 256;
                int cc = idx >> 7, nn = idx & 127;
                As[cc][nn] = xb[(c0 + cc) * HW + nn];
            }
            // B tile: [TC][128], coalesced over c within each code row
#pragma unroll
            for (int r = 0; r < 4; r++) {
                int idx = tid + r * 256;
                int kk = idx >> 3, cc = idx & 7;
                Bs[cc][kk] = emb[(size_t)(k0 + kk) * DIM + c0 + cc];
            }
            __syncthreads();
#pragma unroll
            for (int cc = 0; cc < TC; cc++) {
                float4 a0 = *(const float4*)&As[cc][ty * 8];
                float4 a1 = *(const float4*)&As[cc][ty * 8 + 4];
                float4 b0 = *(const float4*)&Bs[cc][tx * 8];
                float4 b1 = *(const float4*)&Bs[cc][tx * 8 + 4];
                float av[8] = {a0.x, a0.y, a0.z, a0.w, a1.x, a1.y, a1.z, a1.w};
                float bv[8] = {b0.x, b0.y, b0.z, b0.w, b1.x, b1.y, b1.z, b1.w};
#pragma unroll
                for (int i = 0; i < 8; i++)
#pragma unroll
                    for (int j = 0; j < 8; j++)
                        acc[i][j] = __fmaf_rn(av[i], bv[j], acc[i][j]);
            }
        }

        // Epilogue: score = fl(fl(a_n + b_k) - fl(2*c)); running argmin, first-index ties.
        float bk[8];
#pragma unroll
        for (int j = 0; j < 8; j++) bk[j] = g_embsq[k0 + tx * 8 + j];

#pragma unroll
        for (int i = 0; i < 8; i++) {
            int n = ty * 8 + i;
            float an = sA[n];
            float best = CUDART_INF_F;
            int bidx = 0x7fffffff;
#pragma unroll
            for (int j = 0; j < 8; j++) {
                float s = __fsub_rn(__fadd_rn(an, bk[j]), __fmul_rn(2.0f, acc[i][j]));
                if (s < best) { best = s; bidx = k0 + tx * 8 + j; }
            }
            // reduce across the 16 tx lanes owning this row (within a warp half)
#pragma unroll
            for (int m = 1; m < 16; m <<= 1) {
                float ov = __shfl_xor_sync(0xffffffffu, best, m);
                int   oi = __shfl_xor_sync(0xffffffffu, bidx, m);
                if (ov < best || (ov == best && oi < bidx)) { best = ov; bidx = oi; }
            }
            if (tx == 0) {
                if (best < sBest[n]) { sBest[n] = best; sBIdx[n] = bidx; }
            }
        }
    }
    __syncthreads();
    if (tid < TN) g_idx[n0 + tid] = sBIdx[tid];
}

// Outputs: quantized_st (replicating fl(in + fl(q - in))), encodings scatter, loss partials.
__global__ __launch_bounds__(128) void k_out(const float* __restrict__ x,
                                             const float* __restrict__ emb,
                                             float* __restrict__ out) {
    int n = blockIdx.x * 128 + threadIdx.x;
    int b = n >> 10, hw = n & 1023;
    const float* xp = x + (size_t)b * DIM * HW + hw;
    float* qp = out + 1 + (size_t)b * DIM * HW + hw;
    int idx = g_idx[n];
    const float* ep = emb + (size_t)idx * DIM;
    double ssum = 0.0;
#pragma unroll 4
    for (int c = 0; c < DIM; c++) {
        float in = xp[c * HW];
        float q  = ep[c];
        float d  = __fsub_rn(q, in);          // fl(q - in)
        float st = __fadd_rn(in, d);          // fl(in + d)
        qp[c * HW] = st;
        float dd = __fmul_rn(d, d);           // fl(d*d)
        ssum += (double)dd;
    }
    out[1 + (size_t)N_TOTAL * DIM + (size_t)n * KCODES + idx] = 1.0f;

    __shared__ double sred[128];
    sred[threadIdx.x] = ssum;
    __syncthreads();
    for (int s = 64; s > 0; s >>= 1) {
        if (threadIdx.x < s) sred[threadIdx.x] += sred[threadIdx.x + s];
        __syncthreads();
    }
    if (threadIdx.x == 0) g_partial[blockIdx.x] = sred[0];
}

__global__ void k_loss(float* __restrict__ out) {
    __shared__ double sred[256];
    sred[threadIdx.x] = g_partial[threadIdx.x];
    __syncthreads();
    for (int s = 128; s > 0; s >>= 1) {
        if (threadIdx.x < s) sred[threadIdx.x] += sred[threadIdx.x + s];
        __syncthreads();
    }
    if (threadIdx.x == 0) {
        double m = sred[0] / (double)((long long)N_TOTAL * DIM);
        out[0] = (float)(m + 0.25 * m);   // q_latent + commitment * e_latent (equal means)
    }
}

extern "C" void kernel_launch(void* const* d_in, const int* in_sizes, int n_in,
                              void* d_out, int out_size) {
    const float* x = (const float*)d_in[0];
    const float* e = (const float*)d_in[1];
    // defensive: detect swapped input order via element counts
    if (n_in >= 2 && in_sizes[0] == KCODES * DIM && in_sizes[1] == N_TOTAL * DIM) {
        x = (const float*)d_in[1];
        e = (const float*)d_in[0];
    }
    float* out = (float*)d_out;

    k_rowsq<<<N_TOTAL / 256, 256>>>(x);
    k_embsq<<<KCODES / 256, 256>>>(e);

    long long encN = (long long)N_TOTAL * KCODES;
    k_zero<<<(unsigned)((encN + 255) / 256), 256>>>(out + 1 + (size_t)N_TOTAL * DIM, encN);

    k_argmin<<<N_TOTAL / TN, 256>>>(x, e);
    k_out<<<N_TOTAL / 128, 128>>>(x, e, out);
    k_loss<<<1, 256>>>(out);
}